// round 4
// baseline (speedup 1.0000x reference)
#include <cuda_runtime.h>
#include <cuda_bf16.h>

// DepthEmissionRaymarcher: B=2,H=192,W=320,P=128,F=8
// inputs: rays_densities (B,H,W,P,1) f32, rays_features (B,H,W,P,F) f32, lengths (B,H,W,P) f32
// output: concat(depth (B,H,W), features (B,H,W,F)) f32
//
// One warp per ray, persistent grid (single wave), streaming cache hints.
// Pure HBM-roofline kernel: 633 MB of single-use traffic.

constexpr int P_PTS  = 128;
constexpr int F_DIM  = 8;
constexpr int WARPS  = 8;
constexpr int NTHREADS = WARPS * 32;
constexpr int PERSISTENT_CTAS = 152 * 8;   // GB300: 152 SMs, 8 CTAs/SM (reg-limited)

__global__ __launch_bounds__(NTHREADS, 8)
void raymarch_kernel(const float* __restrict__ dens,
                     const float* __restrict__ feat,
                     const float* __restrict__ len,
                     float* __restrict__ out_depth,
                     float* __restrict__ out_feat,
                     int nrays)
{
    __shared__ float sprobs[WARPS][P_PTS];

    const int warp   = threadIdx.x >> 5;
    const int lane   = threadIdx.x & 31;
    const int gwarp  = blockIdx.x * WARPS + warp;
    const int stride = gridDim.x * WARPS;

    for (int ray = gwarp; ray < nrays; ray += stride) {
        // ---- issue density + length loads back-to-back (MLP=2 up front) ----
        const float4* dptr = reinterpret_cast<const float4*>(dens + (size_t)ray * P_PTS);
        const float4* lptr = reinterpret_cast<const float4*>(len  + (size_t)ray * P_PTS);
        float4 d4 = __ldcs(dptr + lane);
        float4 l4 = __ldcs(lptr + lane);
        if (lane == 31) d4.w = 1.0f;   // wall=True: last sample density -> 1

        // local inclusive prefix within the lane's 4 points
        float s0 = d4.x;
        float s1 = s0 + d4.y;
        float s2 = s1 + d4.z;
        float s3 = s2 + d4.w;

        // exclusive warp scan of per-lane totals (Kogge-Stone)
        float t = s3;
        #pragma unroll
        for (int sh = 1; sh < 32; sh <<= 1) {
            float v = __shfl_up_sync(0xffffffffu, t, sh);
            if (lane >= sh) t += v;
        }
        const float off = t - s3;   // exclusive prefix of raw cumsum

        // clamp raw cumsum to 1, diff -> absorption probs
        const float cprev = fminf(off, 1.0f);
        const float c0 = fminf(off + s0, 1.0f);
        const float c1 = fminf(off + s1, 1.0f);
        const float c2 = fminf(off + s2, 1.0f);
        const float c3 = fminf(off + s3, 1.0f);
        const float p0 = c0 - cprev;
        const float p1 = c1 - c0;
        const float p2 = c2 - c1;
        const float p3 = c3 - c2;

        // stage probs for the coalesced feature pass
        reinterpret_cast<float4*>(sprobs[warp])[lane] = make_float4(p0, p1, p2, p3);

        // ---- expected depth ----
        float dsum = p0 * l4.x + p1 * l4.y + p2 * l4.z + p3 * l4.w;
        #pragma unroll
        for (int sh = 16; sh; sh >>= 1)
            dsum += __shfl_xor_sync(0xffffffffu, dsum, sh);

        __syncwarp();

        // ---- expected features: fully coalesced float4 stream ----
        // ray's features = 256 float4s. Iter k: lane l reads float4 index
        // k*32+l (contiguous 512B per instruction) = half (lane parity) of
        // point p = k*16 + (l>>1). Probs broadcast from smem (conflict-free).
        const float4* fptr = reinterpret_cast<const float4*>(feat + (size_t)ray * P_PTS * F_DIM);
        float4 acc = make_float4(0.f, 0.f, 0.f, 0.f);
        #pragma unroll
        for (int k = 0; k < 8; k++) {
            float4 v = __ldcs(fptr + k * 32 + lane);
            float pr = sprobs[warp][k * 16 + (lane >> 1)];
            acc.x += pr * v.x;
            acc.y += pr * v.y;
            acc.z += pr * v.z;
            acc.w += pr * v.w;
        }
        // parity-preserving reduction: even lanes -> lane 0 (feats 0..3),
        // odd lanes -> lane 1 (feats 4..7)
        #pragma unroll
        for (int sh = 2; sh < 32; sh <<= 1) {
            acc.x += __shfl_down_sync(0xffffffffu, acc.x, sh);
            acc.y += __shfl_down_sync(0xffffffffu, acc.y, sh);
            acc.z += __shfl_down_sync(0xffffffffu, acc.z, sh);
            acc.w += __shfl_down_sync(0xffffffffu, acc.w, sh);
        }

        if (lane == 0) out_depth[ray] = dsum;
        if (lane < 2)
            reinterpret_cast<float4*>(out_feat + (size_t)ray * F_DIM)[lane] = acc;

        __syncwarp();   // protect sprobs before next iteration overwrites it
    }
}

extern "C" void kernel_launch(void* const* d_in, const int* in_sizes, int n_in,
                              void* d_out, int out_size)
{
    const float* dens = (const float*)d_in[0];   // (B,H,W,P,1)
    const float* feat = (const float*)d_in[1];   // (B,H,W,P,F)
    const float* len  = (const float*)d_in[2];   // (B,H,W,P)

    const int nrays = in_sizes[2] / P_PTS;       // B*H*W = 122880

    float* out_depth = (float*)d_out;            // first nrays floats
    float* out_feat  = (float*)d_out + nrays;    // then nrays*F floats

    int blocks = PERSISTENT_CTAS;
    int max_blocks = (nrays + WARPS - 1) / WARPS;
    if (blocks > max_blocks) blocks = max_blocks;
    raymarch_kernel<<<blocks, NTHREADS>>>(dens, feat, len, out_depth, out_feat, nrays);
}

// round 5
// speedup vs baseline: 1.0148x; 1.0148x over previous
#include <cuda_runtime.h>
#include <cuda_bf16.h>

// DepthEmissionRaymarcher: B=2,H=192,W=320,P=128,F=8
// inputs: rays_densities (B,H,W,P,1) f32, rays_features (B,H,W,P,F) f32, lengths (B,H,W,P) f32
// output: concat(depth (B,H,W), features (B,H,W,F)) f32
//
// One warp per ray, one ray per warp (non-persistent: measured faster than
// grid-stride). All 10 LDG.128 front-batched into registers so the scan
// executes under feature-load latency. Pure HBM-roofline kernel (633 MB).

constexpr int P_PTS  = 128;
constexpr int F_DIM  = 8;
constexpr int WARPS  = 8;
constexpr int NTHREADS = WARPS * 32;

__global__ __launch_bounds__(NTHREADS, 4)   // allow ~64 regs: 8 prefetched float4s
void raymarch_kernel(const float* __restrict__ dens,
                     const float* __restrict__ feat,
                     const float* __restrict__ len,
                     float* __restrict__ out_depth,
                     float* __restrict__ out_feat,
                     int nrays)
{
    __shared__ float sprobs[WARPS][P_PTS];

    const int warp = threadIdx.x >> 5;
    const int lane = threadIdx.x & 31;
    const int ray  = blockIdx.x * WARPS + warp;
    if (ray >= nrays) return;   // warp-uniform

    // ---- front-batch ALL loads: 2 small + 8 feature float4s (MLP=10) ----
    const float4* dptr = reinterpret_cast<const float4*>(dens + (size_t)ray * P_PTS);
    const float4* lptr = reinterpret_cast<const float4*>(len  + (size_t)ray * P_PTS);
    const float4* fptr = reinterpret_cast<const float4*>(feat + (size_t)ray * P_PTS * F_DIM);

    float4 d4 = __ldcs(dptr + lane);
    float4 l4 = __ldcs(lptr + lane);
    float4 v[8];
    #pragma unroll
    for (int k = 0; k < 8; k++)
        v[k] = __ldcs(fptr + k * 32 + lane);

    if (lane == 31) d4.w = 1.0f;   // wall=True: last sample density -> 1

    // local inclusive prefix within the lane's 4 points
    float s0 = d4.x;
    float s1 = s0 + d4.y;
    float s2 = s1 + d4.z;
    float s3 = s2 + d4.w;

    // exclusive warp scan of per-lane totals (Kogge-Stone)
    float t = s3;
    #pragma unroll
    for (int sh = 1; sh < 32; sh <<= 1) {
        float u = __shfl_up_sync(0xffffffffu, t, sh);
        if (lane >= sh) t += u;
    }
    const float off = t - s3;   // exclusive prefix of raw cumsum

    // clamp raw cumsum to 1, diff -> absorption probs
    const float cprev = fminf(off, 1.0f);
    const float c0 = fminf(off + s0, 1.0f);
    const float c1 = fminf(off + s1, 1.0f);
    const float c2 = fminf(off + s2, 1.0f);
    const float c3 = fminf(off + s3, 1.0f);
    const float p0 = c0 - cprev;
    const float p1 = c1 - c0;
    const float p2 = c2 - c1;
    const float p3 = c3 - c2;

    // stage probs for the feature pass (loads already in flight, so the
    // barrier no longer gates any global traffic)
    reinterpret_cast<float4*>(sprobs[warp])[lane] = make_float4(p0, p1, p2, p3);

    // ---- expected depth ----
    float dsum = p0 * l4.x + p1 * l4.y + p2 * l4.z + p3 * l4.w;
    #pragma unroll
    for (int sh = 16; sh; sh >>= 1)
        dsum += __shfl_xor_sync(0xffffffffu, dsum, sh);

    __syncwarp();

    // ---- expected features from prefetched registers ----
    // v[k] = float4 index k*32+lane = half (lane parity) of point k*16+(lane>>1).
    float4 acc = make_float4(0.f, 0.f, 0.f, 0.f);
    #pragma unroll
    for (int k = 0; k < 8; k++) {
        float pr = sprobs[warp][k * 16 + (lane >> 1)];
        acc.x += pr * v[k].x;
        acc.y += pr * v[k].y;
        acc.z += pr * v[k].z;
        acc.w += pr * v[k].w;
    }
    // parity-preserving reduction: even lanes -> lane 0 (feats 0..3),
    // odd lanes -> lane 1 (feats 4..7)
    #pragma unroll
    for (int sh = 2; sh < 32; sh <<= 1) {
        acc.x += __shfl_down_sync(0xffffffffu, acc.x, sh);
        acc.y += __shfl_down_sync(0xffffffffu, acc.y, sh);
        acc.z += __shfl_down_sync(0xffffffffu, acc.z, sh);
        acc.w += __shfl_down_sync(0xffffffffu, acc.w, sh);
    }

    if (lane == 0) out_depth[ray] = dsum;
    if (lane < 2)
        reinterpret_cast<float4*>(out_feat + (size_t)ray * F_DIM)[lane] = acc;
}

extern "C" void kernel_launch(void* const* d_in, const int* in_sizes, int n_in,
                              void* d_out, int out_size)
{
    const float* dens = (const float*)d_in[0];   // (B,H,W,P,1)
    const float* feat = (const float*)d_in[1];   // (B,H,W,P,F)
    const float* len  = (const float*)d_in[2];   // (B,H,W,P)

    const int nrays = in_sizes[2] / P_PTS;       // B*H*W = 122880

    float* out_depth = (float*)d_out;            // first nrays floats
    float* out_feat  = (float*)d_out + nrays;    // then nrays*F floats

    const int blocks = (nrays + WARPS - 1) / WARPS;
    raymarch_kernel<<<blocks, NTHREADS>>>(dens, feat, len, out_depth, out_feat, nrays);
}

// round 6
// speedup vs baseline: 1.0616x; 1.0461x over previous
#include <cuda_runtime.h>
#include <cuda_bf16.h>

// DepthEmissionRaymarcher: B=2,H=192,W=320,P=128,F=8
// inputs: rays_densities (B,H,W,P,1) f32, rays_features (B,H,W,P,F) f32, lengths (B,H,W,P) f32
// output: concat(depth (B,H,W), features (B,H,W,F)) f32
//
// One warp per ray (non-persistent). Converged at HBM roofline:
// 633 MB single-use traffic / ~7.07 TB/s effective = ~90 us kernel time.
// This round: balanced prefetch (MLP=6, occ ~75%) + streaming stores.

constexpr int P_PTS  = 128;
constexpr int F_DIM  = 8;
constexpr int WARPS  = 8;
constexpr int NTHREADS = WARPS * 32;

__global__ __launch_bounds__(NTHREADS, 6)   // target ~40 regs, 6 CTAs/SM
void raymarch_kernel(const float* __restrict__ dens,
                     const float* __restrict__ feat,
                     const float* __restrict__ len,
                     float* __restrict__ out_depth,
                     float* __restrict__ out_feat,
                     int nrays)
{
    __shared__ float sprobs[WARPS][P_PTS];

    const int warp = threadIdx.x >> 5;
    const int lane = threadIdx.x & 31;
    const int ray  = blockIdx.x * WARPS + warp;
    if (ray >= nrays) return;   // warp-uniform

    // ---- front-batch: densities, lengths, first half of features (MLP=6) ----
    const float4* dptr = reinterpret_cast<const float4*>(dens + (size_t)ray * P_PTS);
    const float4* lptr = reinterpret_cast<const float4*>(len  + (size_t)ray * P_PTS);
    const float4* fptr = reinterpret_cast<const float4*>(feat + (size_t)ray * P_PTS * F_DIM);

    float4 d4 = __ldcs(dptr + lane);
    float4 l4 = __ldcs(lptr + lane);
    float4 v[4];
    #pragma unroll
    for (int k = 0; k < 4; k++)
        v[k] = __ldcs(fptr + k * 32 + lane);

    if (lane == 31) d4.w = 1.0f;   // wall=True: last sample density -> 1

    // local inclusive prefix within the lane's 4 points
    float s0 = d4.x;
    float s1 = s0 + d4.y;
    float s2 = s1 + d4.z;
    float s3 = s2 + d4.w;

    // exclusive warp scan of per-lane totals (Kogge-Stone)
    float t = s3;
    #pragma unroll
    for (int sh = 1; sh < 32; sh <<= 1) {
        float u = __shfl_up_sync(0xffffffffu, t, sh);
        if (lane >= sh) t += u;
    }
    const float off = t - s3;   // exclusive prefix of raw cumsum

    // clamp raw cumsum to 1, diff -> absorption probs
    const float cprev = fminf(off, 1.0f);
    const float c0 = fminf(off + s0, 1.0f);
    const float c1 = fminf(off + s1, 1.0f);
    const float c2 = fminf(off + s2, 1.0f);
    const float c3 = fminf(off + s3, 1.0f);
    const float p0 = c0 - cprev;
    const float p1 = c1 - c0;
    const float p2 = c2 - c1;
    const float p3 = c3 - c2;

    // stage probs for the feature pass
    reinterpret_cast<float4*>(sprobs[warp])[lane] = make_float4(p0, p1, p2, p3);

    // ---- expected depth ----
    float dsum = p0 * l4.x + p1 * l4.y + p2 * l4.z + p3 * l4.w;
    #pragma unroll
    for (int sh = 16; sh; sh >>= 1)
        dsum += __shfl_xor_sync(0xffffffffu, dsum, sh);

    __syncwarp();

    // ---- expected features ----
    // float4 index k*32+lane = half (lane parity) of point k*16+(lane>>1);
    // prob broadcast from smem (conflict-free: pairs of lanes share a word).
    float4 acc = make_float4(0.f, 0.f, 0.f, 0.f);
    #pragma unroll
    for (int k = 0; k < 4; k++) {        // prefetched half
        float pr = sprobs[warp][k * 16 + (lane >> 1)];
        acc.x += pr * v[k].x;
        acc.y += pr * v[k].y;
        acc.z += pr * v[k].z;
        acc.w += pr * v[k].w;
    }
    #pragma unroll
    for (int k = 4; k < 8; k++) {        // streamed half
        float4 w = __ldcs(fptr + k * 32 + lane);
        float pr = sprobs[warp][k * 16 + (lane >> 1)];
        acc.x += pr * w.x;
        acc.y += pr * w.y;
        acc.z += pr * w.z;
        acc.w += pr * w.w;
    }
    // parity-preserving reduction: even lanes -> lane 0 (feats 0..3),
    // odd lanes -> lane 1 (feats 4..7)
    #pragma unroll
    for (int sh = 2; sh < 32; sh <<= 1) {
        acc.x += __shfl_down_sync(0xffffffffu, acc.x, sh);
        acc.y += __shfl_down_sync(0xffffffffu, acc.y, sh);
        acc.z += __shfl_down_sync(0xffffffffu, acc.z, sh);
        acc.w += __shfl_down_sync(0xffffffffu, acc.w, sh);
    }

    if (lane == 0) __stcs(out_depth + ray, dsum);
    if (lane < 2)
        __stcs(reinterpret_cast<float4*>(out_feat + (size_t)ray * F_DIM) + lane, acc);
}

extern "C" void kernel_launch(void* const* d_in, const int* in_sizes, int n_in,
                              void* d_out, int out_size)
{
    const float* dens = (const float*)d_in[0];   // (B,H,W,P,1)
    const float* feat = (const float*)d_in[1];   // (B,H,W,P,F)
    const float* len  = (const float*)d_in[2];   // (B,H,W,P)

    const int nrays = in_sizes[2] / P_PTS;       // B*H*W = 122880

    float* out_depth = (float*)d_out;            // first nrays floats
    float* out_feat  = (float*)d_out + nrays;    // then nrays*F floats

    const int blocks = (nrays + WARPS - 1) / WARPS;
    raymarch_kernel<<<blocks, NTHREADS>>>(dens, feat, len, out_depth, out_feat, nrays);
}